// round 11
// baseline (speedup 1.0000x reference)
#include <cuda_runtime.h>
#include <math.h>
#include <stdint.h>

// ---------------- problem constants ----------------
#define B_    2
#define S_    1024
#define D_    1024
#define G_    8
#define H_    2
#define HD_   64
#define E_    8
#define KTOP  2
#define FF_   4096
#define NT    (B_*S_)          // 2048 tokens
#define NS    (NT*KTOP)        // 4096 slots

// ---------------- device scratch (alloc-free rule) ----------------
__device__ __align__(128) float g_hx [NT*(size_t)D_];          // rmsnorm1 output
__device__ __align__(128) float g_qkv[(size_t)B_*G_*S_*256];   // per (b,g,s): [q(128)|k(64)|v(64)]
__device__ __align__(128) float g_x1 [NT*(size_t)D_];          // x + attn_out
__device__ __align__(128) float g_h2 [NT*(size_t)D_];          // rmsnorm2 output
__device__ __align__(128) float g_act[(size_t)NS*FF_];         // expert hidden
__device__ __align__(128) float g_sout[(size_t)NS*D_];         // per-slot out * gate
__device__ int   g_topi[NT*2];
__device__ float g_gate[NT*2];
__device__ int   g_count[E_], g_offset[E_], g_cursor[E_];
__device__ int   g_slot_token[NS];
__device__ float g_slot_gate[NS];
__device__ int   g_token_slot[NT*2];
__device__ float g_psum[E_];

// ---------------- reset ----------------
__global__ void reset_kernel() {
    int i = threadIdx.x;
    if (i < E_) { g_count[i] = 0; g_cursor[i] = 0; g_psum[i] = 0.f; }
}

// ---------------- rmsnorm (float4: one vector per thread, D=1024/256) -------
__device__ __forceinline__ void rmsnorm_body(const float* __restrict__ xr,
                                             const float* __restrict__ w,
                                             float* __restrict__ orow) {
    int d4 = threadIdx.x;                       // 0..255 float4 index
    float4 v = *(const float4*)(xr + d4*4);
    float ss = v.x*v.x + v.y*v.y + v.z*v.z + v.w*v.w;
    for (int o = 16; o > 0; o >>= 1) ss += __shfl_xor_sync(~0u, ss, o);
    __shared__ float red[8];
    int wid = threadIdx.x >> 5, lane = threadIdx.x & 31;
    if (lane == 0) red[wid] = ss;
    __syncthreads();
    __shared__ float srstd;
    if (threadIdx.x == 0) {
        float s2 = 0.f;
        #pragma unroll
        for (int i = 0; i < 8; i++) s2 += red[i];
        srstd = rsqrtf(s2 / (float)D_ + 1e-6f);
    }
    __syncthreads();
    float r = srstd;
    float4 wv = *(const float4*)(w + d4*4);
    float4 o;
    o.x = wv.x * v.x * r;
    o.y = wv.y * v.y * r;
    o.z = wv.z * v.z * r;
    o.w = wv.w * v.w * r;
    *(float4*)(orow + d4*4) = o;
}

__global__ void rmsnorm1_kernel(const float* __restrict__ x, const float* __restrict__ w) {
    size_t t = blockIdx.x;
    rmsnorm_body(x + t*D_, w, g_hx + t*D_);
}
__global__ void rmsnorm2_kernel(const float* __restrict__ w) {
    size_t t = blockIdx.x;
    rmsnorm_body(g_x1 + t*D_, w, g_h2 + t*D_);
}

// ---------------- tf32 helper ----------------
__device__ __forceinline__ uint32_t f2tf32(float x) {
    uint32_t r;
    asm("cvt.rna.tf32.f32 %0, %1;" : "=r"(r) : "f"(x));
    return r;
}

// ---------------- QKV projection: tf32 mma, 128x128 tile ----------------
// grid(2, NT/128=16, G=8), block 256 (8 warps, each 64x32).
// col block 0 -> Wq[:,0:128]; col block 1 -> [Wk(64) | Wv(64)].
__global__ void __launch_bounds__(256) qkv_mma_kernel(
    const float* __restrict__ Wq,
    const float* __restrict__ Wk,
    const float* __restrict__ Wv)
{
    __shared__ uint32_t sA[2][16][136];
    __shared__ uint32_t sB[2][16][136];

    int g   = blockIdx.z;
    int cb  = blockIdx.x;           // 0 or 1
    int row0 = blockIdx.y * 128;

    int tid  = threadIdx.x;
    int warp = tid >> 5, lane = tid & 31;
    int gq   = lane >> 2, tig = lane & 3;
    int wm   = (warp >> 2) * 64;
    int wn   = (warp & 3) * 32;

    int ar  = tid >> 1, aco = (tid & 1) * 8;   // A: 2 thr/row, 8 k each
    int br  = tid >> 4, bco = (tid & 15) * 8;  // B: 16 thr/k-row, 8 cols each

    const float* Aptr = g_hx + (size_t)(row0 + ar)*D_ + aco;

    const float* Bbase; int ldb;
    if (cb == 0) { Bbase = Wq + (size_t)g*D_*128 + bco; ldb = 128; }
    else if (bco < 64) { Bbase = Wk + (size_t)g*D_*64 + bco; ldb = 64; }
    else               { Bbase = Wv + (size_t)g*D_*64 + (bco - 64); ldb = 64; }
    const float* Bptr = Bbase + (size_t)br*ldb;

    float c[4][4][4];
    #pragma unroll
    for (int i = 0; i < 4; i++)
        #pragma unroll
        for (int j = 0; j < 4; j++)
            #pragma unroll
            for (int q = 0; q < 4; q++) c[i][j][q] = 0.f;

    float4 pa0, pa1, pb0, pb1;
    pa0 = *(const float4*)(Aptr);
    pa1 = *(const float4*)(Aptr + 4);
    pb0 = *(const float4*)(Bptr);
    pb1 = *(const float4*)(Bptr + 4);
    sA[0][aco+0][ar] = f2tf32(pa0.x); sA[0][aco+1][ar] = f2tf32(pa0.y);
    sA[0][aco+2][ar] = f2tf32(pa0.z); sA[0][aco+3][ar] = f2tf32(pa0.w);
    sA[0][aco+4][ar] = f2tf32(pa1.x); sA[0][aco+5][ar] = f2tf32(pa1.y);
    sA[0][aco+6][ar] = f2tf32(pa1.z); sA[0][aco+7][ar] = f2tf32(pa1.w);
    sB[0][br][bco+0] = f2tf32(pb0.x); sB[0][br][bco+1] = f2tf32(pb0.y);
    sB[0][br][bco+2] = f2tf32(pb0.z); sB[0][br][bco+3] = f2tf32(pb0.w);
    sB[0][br][bco+4] = f2tf32(pb1.x); sB[0][br][bco+5] = f2tf32(pb1.y);
    sB[0][br][bco+6] = f2tf32(pb1.z); sB[0][br][bco+7] = f2tf32(pb1.w);
    __syncthreads();

    int buf = 0;
    for (int kt = 16; kt <= D_; kt += 16) {
        if (kt < D_) {
            pa0 = *(const float4*)(Aptr + kt);
            pa1 = *(const float4*)(Aptr + kt + 4);
            pb0 = *(const float4*)(Bptr + (size_t)kt*ldb);
            pb1 = *(const float4*)(Bptr + (size_t)kt*ldb + 4);
        }
        #pragma unroll
        for (int ks = 0; ks < 16; ks += 8) {
            uint32_t af[4][4], bf[4][2];
            #pragma unroll
            for (int mt = 0; mt < 4; mt++) {
                int m = wm + mt*16 + gq;
                af[mt][0] = sA[buf][ks+tig  ][m];
                af[mt][1] = sA[buf][ks+tig  ][m+8];
                af[mt][2] = sA[buf][ks+tig+4][m];
                af[mt][3] = sA[buf][ks+tig+4][m+8];
            }
            #pragma unroll
            for (int nt = 0; nt < 4; nt++) {
                int n = wn + nt*8 + gq;
                bf[nt][0] = sB[buf][ks+tig  ][n];
                bf[nt][1] = sB[buf][ks+tig+4][n];
            }
            #pragma unroll
            for (int mt = 0; mt < 4; mt++)
                #pragma unroll
                for (int nt = 0; nt < 4; nt++)
                    asm volatile(
                        "mma.sync.aligned.m16n8k8.row.col.f32.tf32.tf32.f32 "
                        "{%0,%1,%2,%3}, {%4,%5,%6,%7}, {%8,%9}, {%0,%1,%2,%3};"
                        : "+f"(c[mt][nt][0]), "+f"(c[mt][nt][1]),
                          "+f"(c[mt][nt][2]), "+f"(c[mt][nt][3])
                        : "r"(af[mt][0]), "r"(af[mt][1]), "r"(af[mt][2]), "r"(af[mt][3]),
                          "r"(bf[nt][0]), "r"(bf[nt][1]));
        }
        if (kt < D_) {
            int nb = buf ^ 1;
            sA[nb][aco+0][ar] = f2tf32(pa0.x); sA[nb][aco+1][ar] = f2tf32(pa0.y);
            sA[nb][aco+2][ar] = f2tf32(pa0.z); sA[nb][aco+3][ar] = f2tf32(pa0.w);
            sA[nb][aco+4][ar] = f2tf32(pa1.x); sA[nb][aco+5][ar] = f2tf32(pa1.y);
            sA[nb][aco+6][ar] = f2tf32(pa1.z); sA[nb][aco+7][ar] = f2tf32(pa1.w);
            sB[nb][br][bco+0] = f2tf32(pb0.x); sB[nb][br][bco+1] = f2tf32(pb0.y);
            sB[nb][br][bco+2] = f2tf32(pb0.z); sB[nb][br][bco+3] = f2tf32(pb0.w);
            sB[nb][br][bco+4] = f2tf32(pb1.x); sB[nb][br][bco+5] = f2tf32(pb1.y);
            sB[nb][br][bco+6] = f2tf32(pb1.z); sB[nb][br][bco+7] = f2tf32(pb1.w);
            __syncthreads();
            buf = nb;
        }
    }

    #pragma unroll
    for (int mt = 0; mt < 4; mt++) {
        #pragma unroll
        for (int rr = 0; rr < 2; rr++) {
            int row = row0 + wm + mt*16 + gq + rr*8;
            int b = row >> 10, s = row & 1023;
            int colb = cb*128 + wn + tig*2;
            size_t base = (((size_t)b*G_ + g)*S_ + s)*256 + colb;
            #pragma unroll
            for (int nt = 0; nt < 4; nt++) {
                float2 o;
                o.x = c[mt][nt][rr*2];
                o.y = c[mt][nt][rr*2+1];
                *(float2*)&g_qkv[base + nt*8] = o;
            }
        }
    }
}

// ---------------- RoPE ----------------
__global__ void rope_kernel() {
    int idx = blockIdx.x*256 + threadIdx.x;
    const int total = B_*G_*S_*3*32;
    if (idx >= total) return;
    int i = idx & 31; int r = idx >> 5;
    int which = r % 3; r /= 3;
    int s = r % S_;   r /= S_;
    int g = r % G_;   int b = r / G_;
    float inv = __expf(-(float)(2*i) * (9.210340371976184f / 64.0f));
    float ang = (float)s * inv;
    float c, sn; __sincosf(ang, &sn, &c);
    size_t base = (((size_t)b*G_ + g)*S_ + s)*256 + which*64;
    float a  = g_qkv[base + i];
    float b2 = g_qkv[base + i + 32];
    g_qkv[base + i]      = a*c  - b2*sn;
    g_qkv[base + i + 32] = a*sn + b2*c;
}

// ---------------- attention: chunked online softmax, lane=key ----------------
// grid(B*G*H=32, S/16=64), block 512 (16 warps = 16 queries).
__global__ void __launch_bounds__(512) attn_kernel(const float* __restrict__ x) {
    int h = blockIdx.x % H_;
    int g = (blockIdx.x / H_) % G_;
    int b = blockIdx.x / (H_*G_);
    int warp = threadIdx.x >> 5, lane = threadIdx.x & 31;
    int s = blockIdx.y*16 + warp;
    size_t bg = ((size_t)b*G_ + g)*S_;

    const float* qr = g_qkv + (bg + s)*256 + h*64;
    float q0 = qr[lane], q1 = qr[lane + 32];

    __shared__ float Kt[64][65];   // [dim][key]
    __shared__ float Vs[64][64];   // [key][dim]

    float m = -1e30f, l = 0.f, a0 = 0.f, a1 = 0.f;
    int smax = blockIdx.y*16 + 15;
    const float scale = 0.125f;

    for (int t0 = 0; t0 <= smax; t0 += 64) {
        for (int i = threadIdx.x; i < 64*64; i += 512) {
            int r = i >> 6, c = i & 63;
            size_t p = (bg + t0 + r)*256;
            Kt[c][r] = g_qkv[p + 128 + c];
            Vs[r][c] = g_qkv[p + 192 + c];
        }
        __syncthreads();

        float s0 = 0.f, s1 = 0.f;
        #pragma unroll
        for (int d = 0; d < 64; d++) {
            float qd = __shfl_sync(~0u, (d < 32) ? q0 : q1, d & 31);
            s0 += qd * Kt[d][lane];
            s1 += qd * Kt[d][lane + 32];
        }
        s0 *= scale; s1 *= scale;
        if (t0 + lane      > s) s0 = -1e30f;
        if (t0 + lane + 32 > s) s1 = -1e30f;

        float mc = fmaxf(s0, s1);
        #pragma unroll
        for (int o = 16; o > 0; o >>= 1) mc = fmaxf(mc, __shfl_xor_sync(~0u, mc, o));
        float nm = fmaxf(m, mc);
        float corr = __expf(m - nm);
        float p0 = __expf(s0 - nm);
        float p1 = __expf(s1 - nm);
        float lc = p0 + p1;
        #pragma unroll
        for (int o = 16; o > 0; o >>= 1) lc += __shfl_xor_sync(~0u, lc, o);
        l  = l*corr + lc;
        a0 *= corr;  a1 *= corr;
        m = nm;

        #pragma unroll
        for (int k = 0; k < 32; k++) {
            float pk0 = __shfl_sync(~0u, p0, k);
            float pk1 = __shfl_sync(~0u, p1, k);
            a0 += pk0*Vs[k][lane]      + pk1*Vs[k+32][lane];
            a1 += pk0*Vs[k][lane+32]   + pk1*Vs[k+32][lane+32];
        }
        __syncthreads();
    }
    float invl = 1.f / l;
    size_t ob = ((size_t)b*S_ + s)*D_ + (size_t)(g*H_ + h)*64;
    g_x1[ob + lane]      = x[ob + lane]      + a0*invl;
    g_x1[ob + lane + 32] = x[ob + lane + 32] + a1*invl;
}

// ---------------- router + top-2 ----------------
__global__ void router_kernel(const float* __restrict__ rw) {
    int t = blockIdx.x;
    const float* hr = g_h2 + (size_t)t*D_;
    float acc[E_];
    #pragma unroll
    for (int e = 0; e < E_; e++) acc[e] = 0.f;
    for (int d = threadIdx.x; d < D_; d += 256) {
        float hv = hr[d];
        #pragma unroll
        for (int e = 0; e < E_; e++) acc[e] += hv * rw[d*E_ + e];
    }
    #pragma unroll
    for (int o = 16; o > 0; o >>= 1)
        #pragma unroll
        for (int e = 0; e < E_; e++) acc[e] += __shfl_xor_sync(~0u, acc[e], o);
    __shared__ float red[8][E_];
    int wid = threadIdx.x >> 5, lane = threadIdx.x & 31;
    if (lane == 0)
        #pragma unroll
        for (int e = 0; e < E_; e++) red[wid][e] = acc[e];
    __syncthreads();
    if (threadIdx.x == 0) {
        float logit[E_];
        #pragma unroll
        for (int e = 0; e < E_; e++) {
            float sum = 0.f;
            #pragma unroll
            for (int w = 0; w < 8; w++) sum += red[w][e];
            logit[e] = sum;
        }
        float mx = logit[0];
        #pragma unroll
        for (int e = 1; e < E_; e++) mx = fmaxf(mx, logit[e]);
        float p[E_], sum = 0.f;
        #pragma unroll
        for (int e = 0; e < E_; e++) { p[e] = __expf(logit[e] - mx); sum += p[e]; }
        float inv = 1.f / sum;
        #pragma unroll
        for (int e = 0; e < E_; e++) { p[e] *= inv; atomicAdd(&g_psum[e], p[e]); }
        int i0 = 0;
        #pragma unroll
        for (int e = 1; e < E_; e++) if (p[e] > p[i0]) i0 = e;
        int i1 = -1;
        #pragma unroll
        for (int e = 0; e < E_; e++) {
            if (e == i0) continue;
            if (i1 < 0 || p[e] > p[i1]) i1 = e;
        }
        float v0 = p[i0], v1 = p[i1];
        float inv2 = 1.f / (v0 + v1);
        g_topi[t*2]   = i0;  g_topi[t*2+1] = i1;
        g_gate[t*2]   = v0*inv2;  g_gate[t*2+1] = v1*inv2;
        atomicAdd(&g_count[i0], 1);
        atomicAdd(&g_count[i1], 1);
    }
}

__global__ void offsets_kernel() {
    if (threadIdx.x == 0) {
        int acc = 0;
        #pragma unroll
        for (int e = 0; e < E_; e++) { g_offset[e] = acc; acc += g_count[e]; }
    }
}

__global__ void scatter_kernel() {
    int t = blockIdx.x*256 + threadIdx.x;
    if (t >= NT) return;
    #pragma unroll
    for (int k = 0; k < KTOP; k++) {
        int e = g_topi[t*2 + k];
        int pos = g_offset[e] + atomicAdd(&g_cursor[e], 1);
        g_slot_token[pos] = t;
        g_slot_gate[pos]  = g_gate[t*2 + k];
        g_token_slot[t*2 + k] = pos;
    }
}

// ============ fused gate+up GEMM: tf32 mma, 128x64 tile, SwiGLU epilogue ====
// grid(FF/64=64, NT/128=16, E=8), block 256 (8 warps as 4x2, warp tile 32x32).
// sBg/sBu padded to 72 words/row (72 mod 32 = 8 -> fragment reads bank-free).
__global__ void __launch_bounds__(256) gateup_kernel(
    const float* __restrict__ wg, const float* __restrict__ wu)
{
    int e = blockIdx.z;
    int cnt = g_count[e];
    int row0 = blockIdx.y * 128;
    if (row0 >= cnt) return;
    int off = g_offset[e];

    __shared__ int rows_s[128];
    __shared__ uint32_t sA [2][16][136];
    __shared__ uint32_t sBg[2][16][72];
    __shared__ uint32_t sBu[2][16][72];

    int tid = threadIdx.x;
    if (tid < 128) {
        int r = row0 + tid;
        rows_s[tid] = (r < cnt) ? g_slot_token[off + r] : -1;
    }
    __syncthreads();

    int warp = tid >> 5, lane = tid & 31;
    int gq   = lane >> 2, tig = lane & 3;
    int wm   = (warp >> 1) * 32;     // 4 warp-rows * 32
    int wn   = (warp & 1) * 32;      // 2 warp-cols * 32

    int ar  = tid >> 1, aco = (tid & 1) * 8;   // A: 128 rows x 16 k
    int br  = tid >> 4, bco = (tid & 15) * 4;  // B: 16 k-rows x 64 cols, 1 float4/thr

    int col0 = blockIdx.x * 64;
    int tok = rows_s[ar];
    bool avalid = tok >= 0;
    const float* Aptr = g_h2 + (size_t)(avalid ? tok : 0)*D_ + aco;
    const float* Bg = wg + (size_t)e*D_*FF_ + (size_t)br*FF_ + col0 + bco;
    const float* Bu = wu + (size_t)e*D_*FF_ + (size_t)br*FF_ + col0 + bco;

    float cg[2][4][4], cu[2][4][4];
    #pragma unroll
    for (int i = 0; i < 2; i++)
        #pragma unroll
        for (int j = 0; j < 4; j++)
            #pragma unroll
            for (int q = 0; q < 4; q++) { cg[i][j][q] = 0.f; cu[i][j][q] = 0.f; }

    float4 pa0, pa1, pbg, pbu;
    pa0 = avalid ? *(const float4*)(Aptr)     : make_float4(0.f,0.f,0.f,0.f);
    pa1 = avalid ? *(const float4*)(Aptr + 4) : make_float4(0.f,0.f,0.f,0.f);
    pbg = *(const float4*)(Bg);
    pbu = *(const float4*)(Bu);
    sA[0][aco+0][ar] = f2tf32(pa0.x); sA[0][aco+1][ar] = f2tf32(pa0.y);
    sA[0][aco+2][ar] = f2tf32(pa0.z); sA[0][aco+3][ar] = f2tf32(pa0.w);
    sA[0][aco+4][ar] = f2tf32(pa1.x); sA[0][aco+5][ar] = f2tf32(pa1.y);
    sA[0][aco+6][ar] = f2tf32(pa1.z); sA[0][aco+7][ar] = f2tf32(pa1.w);
    sBg[0][br][bco+0] = f2tf32(pbg.x); sBg[0][br][bco+1] = f2tf32(pbg.y);
    sBg[0][br][bco+2] = f2tf32(pbg.z); sBg[0][br][bco+3] = f2tf32(pbg.w);
    sBu[0][br][bco+0] = f2tf32(pbu.x); sBu[0][br][bco+1] = f2tf32(pbu.y);
    sBu[0][br][bco+2] = f2tf32(pbu.z); sBu[0][br][bco+3] = f2tf32(pbu.w);
    __syncthreads();

    int buf = 0;
    for (int kt = 16; kt <= D_; kt += 16) {
        if (kt < D_) {
            pa0 = avalid ? *(const float4*)(Aptr + kt)     : make_float4(0.f,0.f,0.f,0.f);
            pa1 = avalid ? *(const float4*)(Aptr + kt + 4) : make_float4(0.f,0.f,0.f,0.f);
            pbg = *(const float4*)(Bg + (size_t)kt*FF_);
            pbu = *(const float4*)(Bu + (size_t)kt*FF_);
        }
        #pragma unroll
        for (int ks = 0; ks < 16; ks += 8) {
            uint32_t af[2][4], bg_[4][2], bu_[4][2];
            #pragma unroll
            for (int mt = 0; mt < 2; mt++) {
                int m = wm + mt*16 + gq;
                af[mt][0] = sA[buf][ks+tig  ][m];
                af[mt][1] = sA[buf][ks+tig  ][m+8];
                af[mt][2] = sA[buf][ks+tig+4][m];
                af[mt][3] = sA[buf][ks+tig+4][m+8];
            }
            #pragma unroll
            for (int nt = 0; nt < 4; nt++) {
                int n = wn + nt*8 + gq;
                bg_[nt][0] = sBg[buf][ks+tig  ][n];
                bg_[nt][1] = sBg[buf][ks+tig+4][n];
                bu_[nt][0] = sBu[buf][ks+tig  ][n];
                bu_[nt][1] = sBu[buf][ks+tig+4][n];
            }
            #pragma unroll
            for (int mt = 0; mt < 2; mt++)
                #pragma unroll
                for (int nt = 0; nt < 4; nt++) {
                    asm volatile(
                        "mma.sync.aligned.m16n8k8.row.col.f32.tf32.tf32.f32 "
                        "{%0,%1,%2,%3}, {%4,%5,%6,%7}, {%8,%9}, {%0,%1,%2,%3};"
                        : "+f"(cg[mt][nt][0]), "+f"(cg[mt][nt][1]),
                          "+f"(cg[mt][nt][2]), "+f"(cg[mt][nt][3])
                        : "r"(af[mt][0]), "r"(af[mt][1]), "r"(af[mt][2]), "r"(af[mt][3]),
                          "r"(bg_[nt][0]), "r"(bg_[nt][1]));
                    asm volatile(
                        "mma.sync.aligned.m16n8k8.row.col.f32.tf32.tf32.f32 "
                        "{%0,%1,%2,%3}, {%4,%5,%6,%7}, {%8,%9}, {%0,%1,%2,%3};"
                        : "+f"(cu[mt][nt][0]), "+f"(cu[mt][nt][1]),
                          "+f"(cu[mt][nt][2]), "+f"(cu[mt][nt][3])
                        : "r"(af[mt][0]), "r"(af[mt][1]), "r"(af[mt][2]), "r"(af[mt][3]),
                          "r"(bu_[nt][0]), "r"(bu_[nt][1]));
                }
        }
        if (kt < D_) {
            int nb = buf ^ 1;
            sA[nb][aco+0][ar] = f2tf32(pa0.x); sA[nb][aco+1][ar] = f2tf32(pa0.y);
            sA[nb][aco+2][ar] = f2tf32(pa0.z); sA[nb][aco+3][ar] = f2tf32(pa0.w);
            sA[nb][aco+4][ar] = f2tf32(pa1.x); sA[nb][aco+5][ar] = f2tf32(pa1.y);
            sA[nb][aco+6][ar] = f2tf32(pa1.z); sA[nb][aco+7][ar] = f2tf32(pa1.w);
            sBg[nb][br][bco+0] = f2tf32(pbg.x); sBg[nb][br][bco+1] = f2tf32(pbg.y);
            sBg[nb][br][bco+2] = f2tf32(pbg.z); sBg[nb][br][bco+3] = f2tf32(pbg.w);
            sBu[nb][br][bco+0] = f2tf32(pbu.x); sBu[nb][br][bco+1] = f2tf32(pbu.y);
            sBu[nb][br][bco+2] = f2tf32(pbu.z); sBu[nb][br][bco+3] = f2tf32(pbu.w);
            __syncthreads();
            buf = nb;
        }
    }

    // epilogue: act = silu(gate) * up, written once
    #pragma unroll
    for (int mt = 0; mt < 2; mt++) {
        #pragma unroll
        for (int rr = 0; rr < 2; rr++) {
            int r = row0 + wm + mt*16 + gq + rr*8;
            if (r >= cnt) continue;
            int slot = off + r;
            size_t base = (size_t)slot*FF_ + col0 + wn + tig*2;
            #pragma unroll
            for (int nt = 0; nt < 4; nt++) {
                float gv0 = cg[mt][nt][rr*2], gv1 = cg[mt][nt][rr*2+1];
                float uv0 = cu[mt][nt][rr*2], uv1 = cu[mt][nt][rr*2+1];
                float2 o;
                o.x = (gv0 / (1.f + __expf(-gv0))) * uv0;
                o.y = (gv1 / (1.f + __expf(-gv1))) * uv1;
                *(float2*)&g_act[base + nt*8] = o;
            }
        }
    }
}

// ================= down GEMM: tf32 mma.sync, 128x128x16, double-buffered ====
__global__ void __launch_bounds__(256) down_kernel(const float* __restrict__ wd) {
    int e = blockIdx.z;
    int cnt = g_count[e];
    int row0 = blockIdx.y * 128;
    if (row0 >= cnt) return;
    int off = g_offset[e];
    int col0 = blockIdx.x * 128;
    const float* Bm = wd + (size_t)e*FF_*D_;

    __shared__ uint32_t sA[2][16][136];
    __shared__ uint32_t sB[2][16][136];

    int tid  = threadIdx.x;
    int warp = tid >> 5, lane = tid & 31;
    int gq   = lane >> 2, tig = lane & 3;
    int wm   = (warp >> 2) * 64;
    int wn   = (warp & 3) * 32;

    int ar  = tid >> 1, aco = (tid & 1) * 8;
    int br  = tid >> 4, bco = (tid & 15) * 8;

    int sr = off + row0 + ar;
    bool avalid = (row0 + ar) < cnt;
    if (sr > NS - 1) sr = NS - 1;
    const float* Aptr = g_act + (size_t)sr*FF_ + aco;
    const float* Bptr = Bm + (size_t)br*D_ + col0 + bco;

    float c[4][4][4];
    #pragma unroll
    for (int i = 0; i < 4; i++)
        #pragma unroll
        for (int j = 0; j < 4; j++)
            #pragma unroll
            for (int q = 0; q < 4; q++) c[i][j][q] = 0.f;

    float4 pa0, pa1, pb0, pb1;
    pa0 = avalid ? *(const float4*)(Aptr)     : make_float4(0.f,0.f,0.f,0.f);
    pa1 = avalid ? *(const float4*)(Aptr + 4) : make_float4(0.f,0.f,0.f,0.f);
    pb0 = *(const float4*)(Bptr);
    pb1 = *(const float4*)(Bptr + 4);
    sA[0][aco+0][ar] = f2tf32(pa0.x); sA[0][aco+1][ar] = f2tf32(pa0.y);
    sA[0][aco+2][ar] = f2tf32(pa0.z); sA[0][aco+3][ar] = f2tf32(pa0.w);
    sA[0][aco+4][ar] = f2tf32(pa1.x); sA[0][aco+5][ar] = f2tf32(pa1.y);
    sA[0][aco+6][ar] = f2tf32(pa1.z); sA[0][aco+7][ar] = f2tf32(pa1.w);
    sB[0][br][bco+0] = f2tf32(pb0.x); sB[0][br][bco+1] = f2tf32(pb0.y);
    sB[0][br][bco+2] = f2tf32(pb0.z); sB[0][br][bco+3] = f2tf32(pb0.w);
    sB[0][br][bco+4] = f2tf32(pb1.x); sB[0][br][bco+5] = f2tf32(pb1.y);
    sB[0][br][bco+6] = f2tf32(pb1.z); sB[0][br][bco+7] = f2tf32(pb1.w);
    __syncthreads();

    int buf = 0;
    for (int kt = 16; kt <= FF_; kt += 16) {
        if (kt < FF_) {
            pa0 = avalid ? *(const float4*)(Aptr + kt)     : make_float4(0.f,0.f,0.f,0.f);
            pa1 = avalid ? *(const float4*)(Aptr + kt + 4) : make_float4(0.f,0.f,0.f,0.f);
            pb0 = *(const float4*)(Bptr + (size_t)kt*D_);
            pb1 = *(const float4*)(Bptr + (size_t)kt*D_ + 4);
        }
        #pragma unroll
        for (int ks = 0; ks < 16; ks += 8) {
            uint32_t af[4][4], bf[4][2];
            #pragma unroll
            for (int mt = 0; mt < 4; mt++) {
                int m = wm + mt*16 + gq;
                af[mt][0] = sA[buf][ks+tig  ][m];
                af[mt][1] = sA[buf][ks+tig  ][m+8];
                af[mt][2] = sA[buf][ks+tig+4][m];
                af[mt][3] = sA[buf][ks+tig+4][m+8];
            }
            #pragma unroll
            for (int nt = 0; nt < 4; nt++) {
                int n = wn + nt*8 + gq;
                bf[nt][0] = sB[buf][ks+tig  ][n];
                bf[nt][1] = sB[buf][ks+tig+4][n];
            }
            #pragma unroll
            for (int mt = 0; mt < 4; mt++)
                #pragma unroll
                for (int nt = 0; nt < 4; nt++)
                    asm volatile(
                        "mma.sync.aligned.m16n8k8.row.col.f32.tf32.tf32.f32 "
                        "{%0,%1,%2,%3}, {%4,%5,%6,%7}, {%8,%9}, {%0,%1,%2,%3};"
                        : "+f"(c[mt][nt][0]), "+f"(c[mt][nt][1]),
                          "+f"(c[mt][nt][2]), "+f"(c[mt][nt][3])
                        : "r"(af[mt][0]), "r"(af[mt][1]), "r"(af[mt][2]), "r"(af[mt][3]),
                          "r"(bf[nt][0]), "r"(bf[nt][1]));
        }
        if (kt < FF_) {
            int nb = buf ^ 1;
            sA[nb][aco+0][ar] = f2tf32(pa0.x); sA[nb][aco+1][ar] = f2tf32(pa0.y);
            sA[nb][aco+2][ar] = f2tf32(pa0.z); sA[nb][aco+3][ar] = f2tf32(pa0.w);
            sA[nb][aco+4][ar] = f2tf32(pa1.x); sA[nb][aco+5][ar] = f2tf32(pa1.y);
            sA[nb][aco+6][ar] = f2tf32(pa1.z); sA[nb][aco+7][ar] = f2tf32(pa1.w);
            sB[nb][br][bco+0] = f2tf32(pb0.x); sB[nb][br][bco+1] = f2tf32(pb0.y);
            sB[nb][br][bco+2] = f2tf32(pb0.z); sB[nb][br][bco+3] = f2tf32(pb0.w);
            sB[nb][br][bco+4] = f2tf32(pb1.x); sB[nb][br][bco+5] = f2tf32(pb1.y);
            sB[nb][br][bco+6] = f2tf32(pb1.z); sB[nb][br][bco+7] = f2tf32(pb1.w);
            __syncthreads();
            buf = nb;
        }
    }

    #pragma unroll
    for (int mt = 0; mt < 4; mt++) {
        #pragma unroll
        for (int rr = 0; rr < 2; rr++) {
            int r = row0 + wm + mt*16 + gq + rr*8;
            if (r >= cnt) continue;
            int slot = off + r;
            float gate = g_slot_gate[slot];
            size_t base = (size_t)slot*D_ + col0 + wn + tig*2;
            #pragma unroll
            for (int nt = 0; nt < 4; nt++) {
                float2 o;
                o.x = c[mt][nt][rr*2]   * gate;
                o.y = c[mt][nt][rr*2+1] * gate;
                *(float2*)&g_sout[base + nt*8] = o;
            }
        }
    }
}

// ---------------- final combine (float4) ----------------
__global__ void combine_kernel(float* __restrict__ out) {
    int idx = blockIdx.x*256 + threadIdx.x;     // float4 index
    if (idx >= NT*D_/4) return;
    int t  = idx >> 8;          // D_/4 = 256 float4 per token
    int d4 = idx & 255;
    int s0 = g_token_slot[t*2], s1 = g_token_slot[t*2 + 1];
    float4 a = *(const float4*)&g_x1[(size_t)t*D_ + d4*4];
    float4 b = *(const float4*)&g_sout[(size_t)s0*D_ + d4*4];
    float4 c = *(const float4*)&g_sout[(size_t)s1*D_ + d4*4];
    float4 o;
    o.x = a.x + b.x + c.x;
    o.y = a.y + b.y + c.y;
    o.z = a.z + b.z + c.z;
    o.w = a.w + b.w + c.w;
    *(float4*)&out[(size_t)t*D_ + d4*4] = o;
}

// ---------------- aux loss ----------------
__global__ void aux_kernel(float* __restrict__ out, int out_size) {
    if (threadIdx.x == 0 && out_size > NT*D_) {
        float a = 0.f;
        #pragma unroll
        for (int e = 0; e < E_; e++) {
            float f = (float)g_count[e] / (float)(NT*KTOP);
            float p = g_psum[e] / (float)NT;
            a += f*p;
        }
        out[NT*D_] = (float)E_ * a;
    }
}

// ---------------- launch ----------------
extern "C" void kernel_launch(void* const* d_in, const int* in_sizes, int n_in,
                              void* d_out, int out_size) {
    const float* x   = (const float*)d_in[0];
    const float* n1w = (const float*)d_in[1];
    const float* Wq  = (const float*)d_in[2];
    const float* Wk  = (const float*)d_in[3];
    const float* Wv  = (const float*)d_in[4];
    const float* n2w = (const float*)d_in[5];
    const float* rw  = (const float*)d_in[6];
    const float* wg  = (const float*)d_in[7];
    const float* wu  = (const float*)d_in[8];
    const float* wd  = (const float*)d_in[9];
    float* out = (float*)d_out;

    reset_kernel<<<1, 32>>>();
    rmsnorm1_kernel<<<NT, 256>>>(x, n1w);
    {
        dim3 g(2, NT/128, G_);
        qkv_mma_kernel<<<g, 256>>>(Wq, Wk, Wv);
    }
    rope_kernel<<<(B_*G_*S_*3*32)/256, 256>>>();
    {
        dim3 g(B_*G_*H_, S_/16);
        attn_kernel<<<g, 512>>>(x);
    }
    rmsnorm2_kernel<<<NT, 256>>>(n2w);
    router_kernel<<<NT, 256>>>(rw);
    offsets_kernel<<<1, 32>>>();
    scatter_kernel<<<NT/256, 256>>>();
    {
        dim3 g(FF_/64, NT/128, E_);
        gateup_kernel<<<g, 256>>>(wg, wu);
    }
    {
        dim3 g(D_/128, NT/128, E_);
        down_kernel<<<g, 256>>>(wd);
    }
    combine_kernel<<<(NT*D_/4 + 255)/256, 256>>>(out);
    aux_kernel<<<1, 32>>>(out, out_size);
}

// round 13
// speedup vs baseline: 1.2267x; 1.2267x over previous
#include <cuda_runtime.h>
#include <cuda_bf16.h>
#include <math.h>
#include <stdint.h>

// ---------------- problem constants ----------------
#define B_    2
#define S_    1024
#define D_    1024
#define G_    8
#define H_    2
#define HD_   64
#define E_    8
#define KTOP  2
#define FF_   4096
#define NT    (B_*S_)          // 2048 tokens
#define NS    (NT*KTOP)        // 4096 slots

// ---------------- device scratch (alloc-free rule) ----------------
__device__ __align__(128) float g_hx [NT*(size_t)D_];
__device__ __align__(128) float g_qkv[(size_t)B_*G_*S_*256];
__device__ __align__(128) float g_x1 [NT*(size_t)D_];
__device__ __align__(128) float g_h2 [NT*(size_t)D_];
__device__ __align__(128) float g_act[(size_t)NS*FF_];
__device__ __align__(128) float g_sout[(size_t)NS*D_];
__device__ int   g_topi[NT*2];
__device__ float g_gate[NT*2];
__device__ int   g_count[E_], g_offset[E_], g_cursor[E_];
__device__ int   g_slot_token[NS];
__device__ float g_slot_gate[NS];
__device__ int   g_token_slot[NT*2];
__device__ float g_psum[E_];

// ---------------- reset ----------------
__global__ void reset_kernel() {
    int i = threadIdx.x;
    if (i < E_) { g_count[i] = 0; g_cursor[i] = 0; g_psum[i] = 0.f; }
}

// ---------------- rmsnorm (float4) ----------------
__device__ __forceinline__ void rmsnorm_body(const float* __restrict__ xr,
                                             const float* __restrict__ w,
                                             float* __restrict__ orow) {
    int d4 = threadIdx.x;
    float4 v = *(const float4*)(xr + d4*4);
    float ss = v.x*v.x + v.y*v.y + v.z*v.z + v.w*v.w;
    for (int o = 16; o > 0; o >>= 1) ss += __shfl_xor_sync(~0u, ss, o);
    __shared__ float red[8];
    int wid = threadIdx.x >> 5, lane = threadIdx.x & 31;
    if (lane == 0) red[wid] = ss;
    __syncthreads();
    __shared__ float srstd;
    if (threadIdx.x == 0) {
        float s2 = 0.f;
        #pragma unroll
        for (int i = 0; i < 8; i++) s2 += red[i];
        srstd = rsqrtf(s2 / (float)D_ + 1e-6f);
    }
    __syncthreads();
    float r = srstd;
    float4 wv = *(const float4*)(w + d4*4);
    float4 o;
    o.x = wv.x * v.x * r;
    o.y = wv.y * v.y * r;
    o.z = wv.z * v.z * r;
    o.w = wv.w * v.w * r;
    *(float4*)(orow + d4*4) = o;
}

__global__ void rmsnorm1_kernel(const float* __restrict__ x, const float* __restrict__ w) {
    size_t t = blockIdx.x;
    rmsnorm_body(x + t*D_, w, g_hx + t*D_);
}
__global__ void rmsnorm2_kernel(const float* __restrict__ w) {
    size_t t = blockIdx.x;
    rmsnorm_body(g_x1 + t*D_, w, g_h2 + t*D_);
}

// ---------------- helpers ----------------
__device__ __forceinline__ uint32_t f2tf32(float x) {
    uint32_t r;
    asm("cvt.rna.tf32.f32 %0, %1;" : "=r"(r) : "f"(x));
    return r;
}
__device__ __forceinline__ uint32_t f2bf2(float lo, float hi) {
    __nv_bfloat162 h = __floats2bfloat162_rn(lo, hi);
    return *(uint32_t*)&h;
}

// ---------------- QKV projection: tf32 mma, 128x128 tile --------
__global__ void __launch_bounds__(256) qkv_mma_kernel(
    const float* __restrict__ Wq,
    const float* __restrict__ Wk,
    const float* __restrict__ Wv)
{
    __shared__ uint32_t sA[2][16][136];
    __shared__ uint32_t sB[2][16][136];

    int g   = blockIdx.z;
    int cb  = blockIdx.x;
    int row0 = blockIdx.y * 128;

    int tid  = threadIdx.x;
    int warp = tid >> 5, lane = tid & 31;
    int gq   = lane >> 2, tig = lane & 3;
    int wm   = (warp >> 2) * 64;
    int wn   = (warp & 3) * 32;

    int ar  = tid >> 1, aco = (tid & 1) * 8;
    int br  = tid >> 4, bco = (tid & 15) * 8;

    const float* Aptr = g_hx + (size_t)(row0 + ar)*D_ + aco;

    const float* Bbase; int ldb;
    if (cb == 0) { Bbase = Wq + (size_t)g*D_*128 + bco; ldb = 128; }
    else if (bco < 64) { Bbase = Wk + (size_t)g*D_*64 + bco; ldb = 64; }
    else               { Bbase = Wv + (size_t)g*D_*64 + (bco - 64); ldb = 64; }
    const float* Bptr = Bbase + (size_t)br*ldb;

    float c[4][4][4];
    #pragma unroll
    for (int i = 0; i < 4; i++)
        #pragma unroll
        for (int j = 0; j < 4; j++)
            #pragma unroll
            for (int q = 0; q < 4; q++) c[i][j][q] = 0.f;

    float4 pa0, pa1, pb0, pb1;
    pa0 = *(const float4*)(Aptr);
    pa1 = *(const float4*)(Aptr + 4);
    pb0 = *(const float4*)(Bptr);
    pb1 = *(const float4*)(Bptr + 4);
    sA[0][aco+0][ar] = f2tf32(pa0.x); sA[0][aco+1][ar] = f2tf32(pa0.y);
    sA[0][aco+2][ar] = f2tf32(pa0.z); sA[0][aco+3][ar] = f2tf32(pa0.w);
    sA[0][aco+4][ar] = f2tf32(pa1.x); sA[0][aco+5][ar] = f2tf32(pa1.y);
    sA[0][aco+6][ar] = f2tf32(pa1.z); sA[0][aco+7][ar] = f2tf32(pa1.w);
    sB[0][br][bco+0] = f2tf32(pb0.x); sB[0][br][bco+1] = f2tf32(pb0.y);
    sB[0][br][bco+2] = f2tf32(pb0.z); sB[0][br][bco+3] = f2tf32(pb0.w);
    sB[0][br][bco+4] = f2tf32(pb1.x); sB[0][br][bco+5] = f2tf32(pb1.y);
    sB[0][br][bco+6] = f2tf32(pb1.z); sB[0][br][bco+7] = f2tf32(pb1.w);
    __syncthreads();

    int buf = 0;
    for (int kt = 16; kt <= D_; kt += 16) {
        if (kt < D_) {
            pa0 = *(const float4*)(Aptr + kt);
            pa1 = *(const float4*)(Aptr + kt + 4);
            pb0 = *(const float4*)(Bptr + (size_t)kt*ldb);
            pb1 = *(const float4*)(Bptr + (size_t)kt*ldb + 4);
        }
        #pragma unroll
        for (int ks = 0; ks < 16; ks += 8) {
            uint32_t af[4][4], bf[4][2];
            #pragma unroll
            for (int mt = 0; mt < 4; mt++) {
                int m = wm + mt*16 + gq;
                af[mt][0] = sA[buf][ks+tig  ][m];
                af[mt][1] = sA[buf][ks+tig  ][m+8];
                af[mt][2] = sA[buf][ks+tig+4][m];
                af[mt][3] = sA[buf][ks+tig+4][m+8];
            }
            #pragma unroll
            for (int nt = 0; nt < 4; nt++) {
                int n = wn + nt*8 + gq;
                bf[nt][0] = sB[buf][ks+tig  ][n];
                bf[nt][1] = sB[buf][ks+tig+4][n];
            }
            #pragma unroll
            for (int mt = 0; mt < 4; mt++)
                #pragma unroll
                for (int nt = 0; nt < 4; nt++)
                    asm volatile(
                        "mma.sync.aligned.m16n8k8.row.col.f32.tf32.tf32.f32 "
                        "{%0,%1,%2,%3}, {%4,%5,%6,%7}, {%8,%9}, {%0,%1,%2,%3};"
                        : "+f"(c[mt][nt][0]), "+f"(c[mt][nt][1]),
                          "+f"(c[mt][nt][2]), "+f"(c[mt][nt][3])
                        : "r"(af[mt][0]), "r"(af[mt][1]), "r"(af[mt][2]), "r"(af[mt][3]),
                          "r"(bf[nt][0]), "r"(bf[nt][1]));
        }
        if (kt < D_) {
            int nb = buf ^ 1;
            sA[nb][aco+0][ar] = f2tf32(pa0.x); sA[nb][aco+1][ar] = f2tf32(pa0.y);
            sA[nb][aco+2][ar] = f2tf32(pa0.z); sA[nb][aco+3][ar] = f2tf32(pa0.w);
            sA[nb][aco+4][ar] = f2tf32(pa1.x); sA[nb][aco+5][ar] = f2tf32(pa1.y);
            sA[nb][aco+6][ar] = f2tf32(pa1.z); sA[nb][aco+7][ar] = f2tf32(pa1.w);
            sB[nb][br][bco+0] = f2tf32(pb0.x); sB[nb][br][bco+1] = f2tf32(pb0.y);
            sB[nb][br][bco+2] = f2tf32(pb0.z); sB[nb][br][bco+3] = f2tf32(pb0.w);
            sB[nb][br][bco+4] = f2tf32(pb1.x); sB[nb][br][bco+5] = f2tf32(pb1.y);
            sB[nb][br][bco+6] = f2tf32(pb1.z); sB[nb][br][bco+7] = f2tf32(pb1.w);
            __syncthreads();
            buf = nb;
        }
    }

    #pragma unroll
    for (int mt = 0; mt < 4; mt++) {
        #pragma unroll
        for (int rr = 0; rr < 2; rr++) {
            int row = row0 + wm + mt*16 + gq + rr*8;
            int b = row >> 10, s = row & 1023;
            int colb = cb*128 + wn + tig*2;
            size_t base = (((size_t)b*G_ + g)*S_ + s)*256 + colb;
            #pragma unroll
            for (int nt = 0; nt < 4; nt++) {
                float2 o;
                o.x = c[mt][nt][rr*2];
                o.y = c[mt][nt][rr*2+1];
                *(float2*)&g_qkv[base + nt*8] = o;
            }
        }
    }
}

// ---------------- RoPE ----------------
__global__ void rope_kernel() {
    int idx = blockIdx.x*256 + threadIdx.x;
    const int total = B_*G_*S_*3*32;
    if (idx >= total) return;
    int i = idx & 31; int r = idx >> 5;
    int which = r % 3; r /= 3;
    int s = r % S_;   r /= S_;
    int g = r % G_;   int b = r / G_;
    float inv = __expf(-(float)(2*i) * (9.210340371976184f / 64.0f));
    float ang = (float)s * inv;
    float c, sn; __sincosf(ang, &sn, &c);
    size_t base = (((size_t)b*G_ + g)*S_ + s)*256 + which*64;
    float a  = g_qkv[base + i];
    float b2 = g_qkv[base + i + 32];
    g_qkv[base + i]      = a*c  - b2*sn;
    g_qkv[base + i + 32] = a*sn + b2*c;
}

// ---------------- attention ----------------
__global__ void __launch_bounds__(512) attn_kernel(const float* __restrict__ x) {
    int h = blockIdx.x % H_;
    int g = (blockIdx.x / H_) % G_;
    int b = blockIdx.x / (H_*G_);
    int warp = threadIdx.x >> 5, lane = threadIdx.x & 31;
    int s = blockIdx.y*16 + warp;
    size_t bg = ((size_t)b*G_ + g)*S_;

    const float* qr = g_qkv + (bg + s)*256 + h*64;
    float q0 = qr[lane], q1 = qr[lane + 32];

    __shared__ float Kt[64][65];
    __shared__ float Vs[64][64];

    float m = -1e30f, l = 0.f, a0 = 0.f, a1 = 0.f;
    int smax = blockIdx.y*16 + 15;
    const float scale = 0.125f;

    for (int t0 = 0; t0 <= smax; t0 += 64) {
        for (int i = threadIdx.x; i < 64*64; i += 512) {
            int r = i >> 6, c = i & 63;
            size_t p = (bg + t0 + r)*256;
            Kt[c][r] = g_qkv[p + 128 + c];
            Vs[r][c] = g_qkv[p + 192 + c];
        }
        __syncthreads();

        float s0 = 0.f, s1 = 0.f;
        #pragma unroll
        for (int d = 0; d < 64; d++) {
            float qd = __shfl_sync(~0u, (d < 32) ? q0 : q1, d & 31);
            s0 += qd * Kt[d][lane];
            s1 += qd * Kt[d][lane + 32];
        }
        s0 *= scale; s1 *= scale;
        if (t0 + lane      > s) s0 = -1e30f;
        if (t0 + lane + 32 > s) s1 = -1e30f;

        float mc = fmaxf(s0, s1);
        #pragma unroll
        for (int o = 16; o > 0; o >>= 1) mc = fmaxf(mc, __shfl_xor_sync(~0u, mc, o));
        float nm = fmaxf(m, mc);
        float corr = __expf(m - nm);
        float p0 = __expf(s0 - nm);
        float p1 = __expf(s1 - nm);
        float lc = p0 + p1;
        #pragma unroll
        for (int o = 16; o > 0; o >>= 1) lc += __shfl_xor_sync(~0u, lc, o);
        l  = l*corr + lc;
        a0 *= corr;  a1 *= corr;
        m = nm;

        #pragma unroll
        for (int k = 0; k < 32; k++) {
            float pk0 = __shfl_sync(~0u, p0, k);
            float pk1 = __shfl_sync(~0u, p1, k);
            a0 += pk0*Vs[k][lane]      + pk1*Vs[k+32][lane];
            a1 += pk0*Vs[k][lane+32]   + pk1*Vs[k+32][lane+32];
        }
        __syncthreads();
    }
    float invl = 1.f / l;
    size_t ob = ((size_t)b*S_ + s)*D_ + (size_t)(g*H_ + h)*64;
    g_x1[ob + lane]      = x[ob + lane]      + a0*invl;
    g_x1[ob + lane + 32] = x[ob + lane + 32] + a1*invl;
}

// ---------------- router + top-2 ----------------
__global__ void router_kernel(const float* __restrict__ rw) {
    int t = blockIdx.x;
    const float* hr = g_h2 + (size_t)t*D_;
    float acc[E_];
    #pragma unroll
    for (int e = 0; e < E_; e++) acc[e] = 0.f;
    for (int d = threadIdx.x; d < D_; d += 256) {
        float hv = hr[d];
        #pragma unroll
        for (int e = 0; e < E_; e++) acc[e] += hv * rw[d*E_ + e];
    }
    #pragma unroll
    for (int o = 16; o > 0; o >>= 1)
        #pragma unroll
        for (int e = 0; e < E_; e++) acc[e] += __shfl_xor_sync(~0u, acc[e], o);
    __shared__ float red[8][E_];
    int wid = threadIdx.x >> 5, lane = threadIdx.x & 31;
    if (lane == 0)
        #pragma unroll
        for (int e = 0; e < E_; e++) red[wid][e] = acc[e];
    __syncthreads();
    if (threadIdx.x == 0) {
        float logit[E_];
        #pragma unroll
        for (int e = 0; e < E_; e++) {
            float sum = 0.f;
            #pragma unroll
            for (int w = 0; w < 8; w++) sum += red[w][e];
            logit[e] = sum;
        }
        float mx = logit[0];
        #pragma unroll
        for (int e = 1; e < E_; e++) mx = fmaxf(mx, logit[e]);
        float p[E_], sum = 0.f;
        #pragma unroll
        for (int e = 0; e < E_; e++) { p[e] = __expf(logit[e] - mx); sum += p[e]; }
        float inv = 1.f / sum;
        #pragma unroll
        for (int e = 0; e < E_; e++) { p[e] *= inv; atomicAdd(&g_psum[e], p[e]); }
        int i0 = 0;
        #pragma unroll
        for (int e = 1; e < E_; e++) if (p[e] > p[i0]) i0 = e;
        int i1 = -1;
        #pragma unroll
        for (int e = 0; e < E_; e++) {
            if (e == i0) continue;
            if (i1 < 0 || p[e] > p[i1]) i1 = e;
        }
        float v0 = p[i0], v1 = p[i1];
        float inv2 = 1.f / (v0 + v1);
        g_topi[t*2]   = i0;  g_topi[t*2+1] = i1;
        g_gate[t*2]   = v0*inv2;  g_gate[t*2+1] = v1*inv2;
        atomicAdd(&g_count[i0], 1);
        atomicAdd(&g_count[i1], 1);
    }
}

__global__ void offsets_kernel() {
    if (threadIdx.x == 0) {
        int acc = 0;
        #pragma unroll
        for (int e = 0; e < E_; e++) { g_offset[e] = acc; acc += g_count[e]; }
    }
}

__global__ void scatter_kernel() {
    int t = blockIdx.x*256 + threadIdx.x;
    if (t >= NT) return;
    #pragma unroll
    for (int k = 0; k < KTOP; k++) {
        int e = g_topi[t*2 + k];
        int pos = g_offset[e] + atomicAdd(&g_cursor[e], 1);
        g_slot_token[pos] = t;
        g_slot_gate[pos]  = g_gate[t*2 + k];
        g_token_slot[t*2 + k] = pos;
    }
}

// ======= fused gate+up GEMM: bf16 m16n8k16, 128x64 tile, SwiGLU epilogue ====
__global__ void __launch_bounds__(256) gateup_kernel(
    const float* __restrict__ wg, const float* __restrict__ wu)
{
    int e = blockIdx.z;
    int cnt = g_count[e];
    int row0 = blockIdx.y * 128;
    if (row0 >= cnt) return;
    int off = g_offset[e];

    __shared__ int rows_s[128];
    __shared__ uint32_t sA[2][8][136];
    __shared__ uint32_t sB[2][2][8][72];   // [buf][g/u][kpair][n]

    int tid = threadIdx.x;
    if (tid < 128) {
        int r = row0 + tid;
        rows_s[tid] = (r < cnt) ? g_slot_token[off + r] : -1;
    }
    __syncthreads();

    int warp = tid >> 5, lane = tid & 31;
    int gq   = lane >> 2, tig = lane & 3;
    int wm   = (warp >> 1) * 32;
    int wn   = (warp & 1) * 32;

    int ar  = tid >> 1, aco = (tid & 1) * 8, akp = (tid & 1) * 4;
    int which = tid >> 7;
    int bt = tid & 127;
    int bkp = bt >> 4, bn4 = (bt & 15) * 4;

    int col0 = blockIdx.x * 64;
    int tok = rows_s[ar];
    bool avalid = tok >= 0;
    const float* Aptr = g_h2 + (size_t)(avalid ? tok : 0)*D_ + aco;
    const float* Bsel = (which ? wu : wg) + (size_t)e*D_*FF_ + col0 + bn4;
    const float* Bp0 = Bsel + (size_t)(2*bkp    )*FF_;
    const float* Bp1 = Bsel + (size_t)(2*bkp + 1)*FF_;

    float cg[2][4][4], cu[2][4][4];
    #pragma unroll
    for (int i = 0; i < 2; i++)
        #pragma unroll
        for (int j = 0; j < 4; j++)
            #pragma unroll
            for (int q = 0; q < 4; q++) { cg[i][j][q] = 0.f; cu[i][j][q] = 0.f; }

    float4 pa0, pa1, r0, r1;
    pa0 = avalid ? *(const float4*)(Aptr)     : make_float4(0.f,0.f,0.f,0.f);
    pa1 = avalid ? *(const float4*)(Aptr + 4) : make_float4(0.f,0.f,0.f,0.f);
    r0 = *(const float4*)(Bp0);
    r1 = *(const float4*)(Bp1);
    sA[0][akp+0][ar] = f2bf2(pa0.x, pa0.y);
    sA[0][akp+1][ar] = f2bf2(pa0.z, pa0.w);
    sA[0][akp+2][ar] = f2bf2(pa1.x, pa1.y);
    sA[0][akp+3][ar] = f2bf2(pa1.z, pa1.w);
    sB[0][which][bkp][bn4+0] = f2bf2(r0.x, r1.x);
    sB[0][which][bkp][bn4+1] = f2bf2(r0.y, r1.y);
    sB[0][which][bkp][bn4+2] = f2bf2(r0.z, r1.z);
    sB[0][which][bkp][bn4+3] = f2bf2(r0.w, r1.w);
    __syncthreads();

    int buf = 0;
    for (int kt = 16; kt <= D_; kt += 16) {
        if (kt < D_) {
            pa0 = avalid ? *(const float4*)(Aptr + kt)     : make_float4(0.f,0.f,0.f,0.f);
            pa1 = avalid ? *(const float4*)(Aptr + kt + 4) : make_float4(0.f,0.f,0.f,0.f);
            r0 = *(const float4*)(Bp0 + (size_t)kt*FF_);
            r1 = *(const float4*)(Bp1 + (size_t)kt*FF_);
        }
        {
            uint32_t af[2][4], bg_[4][2], bu_[4][2];
            #pragma unroll
            for (int mt = 0; mt < 2; mt++) {
                int m = wm + mt*16 + gq;
                af[mt][0] = sA[buf][tig  ][m];
                af[mt][1] = sA[buf][tig  ][m+8];
                af[mt][2] = sA[buf][tig+4][m];
                af[mt][3] = sA[buf][tig+4][m+8];
            }
            #pragma unroll
            for (int nt = 0; nt < 4; nt++) {
                int n = wn + nt*8 + gq;
                bg_[nt][0] = sB[buf][0][tig  ][n];
                bg_[nt][1] = sB[buf][0][tig+4][n];
                bu_[nt][0] = sB[buf][1][tig  ][n];
                bu_[nt][1] = sB[buf][1][tig+4][n];
            }
            #pragma unroll
            for (int mt = 0; mt < 2; mt++)
                #pragma unroll
                for (int nt = 0; nt < 4; nt++) {
                    asm volatile(
                        "mma.sync.aligned.m16n8k16.row.col.f32.bf16.bf16.f32 "
                        "{%0,%1,%2,%3}, {%4,%5,%6,%7}, {%8,%9}, {%0,%1,%2,%3};"
                        : "+f"(cg[mt][nt][0]), "+f"(cg[mt][nt][1]),
                          "+f"(cg[mt][nt][2]), "+f"(cg[mt][nt][3])
                        : "r"(af[mt][0]), "r"(af[mt][1]), "r"(af[mt][2]), "r"(af[mt][3]),
                          "r"(bg_[nt][0]), "r"(bg_[nt][1]));
                    asm volatile(
                        "mma.sync.aligned.m16n8k16.row.col.f32.bf16.bf16.f32 "
                        "{%0,%1,%2,%3}, {%4,%5,%6,%7}, {%8,%9}, {%0,%1,%2,%3};"
                        : "+f"(cu[mt][nt][0]), "+f"(cu[mt][nt][1]),
                          "+f"(cu[mt][nt][2]), "+f"(cu[mt][nt][3])
                        : "r"(af[mt][0]), "r"(af[mt][1]), "r"(af[mt][2]), "r"(af[mt][3]),
                          "r"(bu_[nt][0]), "r"(bu_[nt][1]));
                }
        }
        if (kt < D_) {
            int nb = buf ^ 1;
            sA[nb][akp+0][ar] = f2bf2(pa0.x, pa0.y);
            sA[nb][akp+1][ar] = f2bf2(pa0.z, pa0.w);
            sA[nb][akp+2][ar] = f2bf2(pa1.x, pa1.y);
            sA[nb][akp+3][ar] = f2bf2(pa1.z, pa1.w);
            sB[nb][which][bkp][bn4+0] = f2bf2(r0.x, r1.x);
            sB[nb][which][bkp][bn4+1] = f2bf2(r0.y, r1.y);
            sB[nb][which][bkp][bn4+2] = f2bf2(r0.z, r1.z);
            sB[nb][which][bkp][bn4+3] = f2bf2(r0.w, r1.w);
            __syncthreads();
            buf = nb;
        }
    }

    // epilogue: act = silu(gate) * up
    #pragma unroll
    for (int mt = 0; mt < 2; mt++) {
        #pragma unroll
        for (int rr = 0; rr < 2; rr++) {
            int r = row0 + wm + mt*16 + gq + rr*8;
            if (r >= cnt) continue;
            int slot = off + r;
            size_t base = (size_t)slot*FF_ + col0 + wn + tig*2;
            #pragma unroll
            for (int nt = 0; nt < 4; nt++) {
                float gv0 = cg[mt][nt][rr*2], gv1 = cg[mt][nt][rr*2+1];
                float uv0 = cu[mt][nt][rr*2], uv1 = cu[mt][nt][rr*2+1];
                float2 o;
                o.x = (gv0 / (1.f + __expf(-gv0))) * uv0;
                o.y = (gv1 / (1.f + __expf(-gv1))) * uv1;
                *(float2*)&g_act[base + nt*8] = o;
            }
        }
    }
}

// ================= down GEMM: bf16 m16n8k16, 128x128x16, double-buffered ====
__global__ void __launch_bounds__(256) down_kernel(const float* __restrict__ wd) {
    int e = blockIdx.z;
    int cnt = g_count[e];
    int row0 = blockIdx.y * 128;
    if (row0 >= cnt) return;
    int off = g_offset[e];
    int col0 = blockIdx.x * 128;
    const float* Bm = wd + (size_t)e*FF_*D_;

    __shared__ uint32_t sA[2][8][136];
    __shared__ uint32_t sB[2][8][136];

    int tid  = threadIdx.x;
    int warp = tid >> 5, lane = tid & 31;
    int gq   = lane >> 2, tig = lane & 3;
    int wm   = (warp >> 2) * 64;
    int wn   = (warp & 3) * 32;

    int ar  = tid >> 1, aco = (tid & 1) * 8, akp = (tid & 1) * 4;
    int bkp = tid >> 5, bn4 = (tid & 31) * 4;

    int sr = off + row0 + ar;
    bool avalid = (row0 + ar) < cnt;
    if (sr > NS - 1) sr = NS - 1;
    const float* Aptr = g_act + (size_t)sr*FF_ + aco;
    const float* Bp0 = Bm + (size_t)(2*bkp    )*D_ + col0 + bn4;
    const float* Bp1 = Bm + (size_t)(2*bkp + 1)*D_ + col0 + bn4;

    float c[4][4][4];
    #pragma unroll
    for (int i = 0; i < 4; i++)
        #pragma unroll
        for (int j = 0; j < 4; j++)
            #pragma unroll
            for (int q = 0; q < 4; q++) c[i][j][q] = 0.f;

    float4 pa0, pa1, r0, r1;
    pa0 = avalid ? *(const float4*)(Aptr)     : make_float4(0.f,0.f,0.f,0.f);
    pa1 = avalid ? *(const float4*)(Aptr + 4) : make_float4(0.f,0.f,0.f,0.f);
    r0 = *(const float4*)(Bp0);
    r1 = *(const float4*)(Bp1);
    sA[0][akp+0][ar] = f2bf2(pa0.x, pa0.y);
    sA[0][akp+1][ar] = f2bf2(pa0.z, pa0.w);
    sA[0][akp+2][ar] = f2bf2(pa1.x, pa1.y);
    sA[0][akp+3][ar] = f2bf2(pa1.z, pa1.w);
    sB[0][bkp][bn4+0] = f2bf2(r0.x, r1.x);
    sB[0][bkp][bn4+1] = f2bf2(r0.y, r1.y);
    sB[0][bkp][bn4+2] = f2bf2(r0.z, r1.z);
    sB[0][bkp][bn4+3] = f2bf2(r0.w, r1.w);
    __syncthreads();

    int buf = 0;
    for (int kt = 16; kt <= FF_; kt += 16) {
        if (kt < FF_) {
            pa0 = avalid ? *(const float4*)(Aptr + kt)     : make_float4(0.f,0.f,0.f,0.f);
            pa1 = avalid ? *(const float4*)(Aptr + kt + 4) : make_float4(0.f,0.f,0.f,0.f);
            r0 = *(const float4*)(Bp0 + (size_t)kt*D_);
            r1 = *(const float4*)(Bp1 + (size_t)kt*D_);
        }
        {
            uint32_t af[4][4], bf[4][2];
            #pragma unroll
            for (int mt = 0; mt < 4; mt++) {
                int m = wm + mt*16 + gq;
                af[mt][0] = sA[buf][tig  ][m];
                af[mt][1] = sA[buf][tig  ][m+8];
                af[mt][2] = sA[buf][tig+4][m];
                af[mt][3] = sA[buf][tig+4][m+8];
            }
            #pragma unroll
            for (int nt = 0; nt < 4; nt++) {
                int n = wn + nt*8 + gq;
                bf[nt][0] = sB[buf][tig  ][n];
                bf[nt][1] = sB[buf][tig+4][n];
            }
            #pragma unroll
            for (int mt = 0; mt < 4; mt++)
                #pragma unroll
                for (int nt = 0; nt < 4; nt++)
                    asm volatile(
                        "mma.sync.aligned.m16n8k16.row.col.f32.bf16.bf16.f32 "
                        "{%0,%1,%2,%3}, {%4,%5,%6,%7}, {%8,%9}, {%0,%1,%2,%3};"
                        : "+f"(c[mt][nt][0]), "+f"(c[mt][nt][1]),
                          "+f"(c[mt][nt][2]), "+f"(c[mt][nt][3])
                        : "r"(af[mt][0]), "r"(af[mt][1]), "r"(af[mt][2]), "r"(af[mt][3]),
                          "r"(bf[nt][0]), "r"(bf[nt][1]));
        }
        if (kt < FF_) {
            int nb = buf ^ 1;
            sA[nb][akp+0][ar] = f2bf2(pa0.x, pa0.y);
            sA[nb][akp+1][ar] = f2bf2(pa0.z, pa0.w);
            sA[nb][akp+2][ar] = f2bf2(pa1.x, pa1.y);
            sA[nb][akp+3][ar] = f2bf2(pa1.z, pa1.w);
            sB[nb][bkp][bn4+0] = f2bf2(r0.x, r1.x);
            sB[nb][bkp][bn4+1] = f2bf2(r0.y, r1.y);
            sB[nb][bkp][bn4+2] = f2bf2(r0.z, r1.z);
            sB[nb][bkp][bn4+3] = f2bf2(r0.w, r1.w);
            __syncthreads();
            buf = nb;
        }
    }

    #pragma unroll
    for (int mt = 0; mt < 4; mt++) {
        #pragma unroll
        for (int rr = 0; rr < 2; rr++) {
            int r = row0 + wm + mt*16 + gq + rr*8;
            if (r >= cnt) continue;
            int slot = off + r;
            float gate = g_slot_gate[slot];
            size_t base = (size_t)slot*D_ + col0 + wn + tig*2;
            #pragma unroll
            for (int nt = 0; nt < 4; nt++) {
                float2 o;
                o.x = c[mt][nt][rr*2]   * gate;
                o.y = c[mt][nt][rr*2+1] * gate;
                *(float2*)&g_sout[base + nt*8] = o;
            }
        }
    }
}

// ---------------- final combine (float4) ----------------
__global__ void combine_kernel(float* __restrict__ out) {
    int idx = blockIdx.x*256 + threadIdx.x;
    if (idx >= NT*D_/4) return;
    int t  = idx >> 8;
    int d4 = idx & 255;
    int s0 = g_token_slot[t*2], s1 = g_token_slot[t*2 + 1];
    float4 a = *(const float4*)&g_x1[(size_t)t*D_ + d4*4];
    float4 b = *(const float4*)&g_sout[(size_t)s0*D_ + d4*4];
    float4 c = *(const float4*)&g_sout[(size_t)s1*D_ + d4*4];
    float4 o;
    o.x = a.x + b.x + c.x;
    o.y = a.y + b.y + c.y;
    o.z = a.z + b.z + c.z;
    o.w = a.w + b.w + c.w;
    *(float4*)&out[(size_t)t*D_ + d4*4] = o;
}

// ---------------- aux loss ----------------
__global__ void aux_kernel(float* __restrict__ out, int out_size) {
    if (threadIdx.x == 0 && out_size > NT*D_) {
        float a = 0.f;
        #pragma unroll
        for (int e = 0; e < E_; e++) {
            float f = (float)g_count[e] / (float)(NT*KTOP);
            float p = g_psum[e] / (float)NT;
            a += f*p;
        }
        out[NT*D_] = (float)E_ * a;
    }
}

// ---------------- launch ----------------
extern "C" void kernel_launch(void* const* d_in, const int* in_sizes, int n_in,
                              void* d_out, int out_size) {
    const float* x   = (const float*)d_in[0];
    const float* n1w = (const float*)d_in[1];
    const float* Wq  = (const float*)d_in[2];
    const float* Wk  = (const float*)d_in[3];
    const float* Wv  = (const float*)d_in[4];
    const float* n2w = (const float*)d_in[5];
    const float* rw  = (const float*)d_in[6];
    const float* wg  = (const float*)d_in[7];
    const float* wu  = (const float*)d_in[8];
    const float* wd  = (const float*)d_in[9];
    float* out = (float*)d_out;

    reset_kernel<<<1, 32>>>();
    rmsnorm1_kernel<<<NT, 256>>>(x, n1w);
    {
        dim3 g(2, NT/128, G_);
        qkv_mma_kernel<<<g, 256>>>(Wq, Wk, Wv);
    }
    rope_kernel<<<(B_*G_*S_*3*32)/256, 256>>>();
    {
        dim3 g(B_*G_*H_, S_/16);
        attn_kernel<<<g, 512>>>(x);
    }
    rmsnorm2_kernel<<<NT, 256>>>(n2w);
    router_kernel<<<NT, 256>>>(rw);
    offsets_kernel<<<1, 32>>>();
    scatter_kernel<<<NT/256, 256>>>();
    {
        dim3 g(FF_/64, NT/128, E_);
        gateup_kernel<<<g, 256>>>(wg, wu);
    }
    {
        dim3 g(D_/128, NT/128, E_);
        down_kernel<<<g, 256>>>(wd);
    }
    combine_kernel<<<(NT*D_/4 + 255)/256, 256>>>(out);
    aux_kernel<<<1, 32>>>(out, out_size);
}